// round 11
// baseline (speedup 1.0000x reference)
#include <cuda_runtime.h>

#define B_TOTAL   131072
#define NBLOCKS   2048
#define NTHREADS  64
#define FULL      0xFFFFFFFFu

// deterministic two-stage reduction scratch (no allocation allowed)
__device__ double   g_partials[NBLOCKS * 2];
__device__ unsigned g_count = 0;

__device__ __forceinline__ float fsqrt_approx(float x) {
    float r; asm("sqrt.approx.f32 %0, %1;" : "=f"(r) : "f"(x)); return r;
}

__global__ __launch_bounds__(NTHREADS)
void constraint_loss_fused(const float* __restrict__ pred,
                           const float* __restrict__ tgt,
                           const float* __restrict__ inp,
                           float* __restrict__ out)
{
    __shared__ double s_red[2][2];
    __shared__ bool   s_is_last;

    const int tid  = threadIdx.x;
    const int lane = tid & 31;
    const int row  = blockIdx.x * NTHREADS + tid;   // one thread = one row

    const float4* p4 = (const float4*)(pred + (size_t)row * 240);
    const float4* t4 = (const float4*)(tgt  + (size_t)row * 240);
    const float*  ir = inp + (size_t)row * 13;

    // initial state + obstacles (13 scalar LDGs, off critical path)
    float4 prev = make_float4(ir[0], ir[1], ir[2], ir[3]);
    float o0x = ir[4],  o0y = ir[5],  q0 = ir[6]  + 2.0f;
    float o1x = ir[7],  o1y = ir[8],  q1 = ir[9]  + 2.0f;
    float o2x = ir[10], o2y = ir[11], q2 = ir[12] + 2.0f;
    float rad0 = q0 * q0, rad1 = q1 * q1, rad2 = q2 * q2;

    float mse = 0.f, ob = 0.f;
    float r0 = 0.f, r1 = 0.f, r2 = 0.f, r3 = 0.f;

    float4 u4, tu4;                 // carries u_k,u_{k+1} across odd steps

    #pragma unroll 4
    for (int k = 0; k < 40; ++k) {
        float4 x  = p4[k];          // x_k
        float4 tx = t4[k];

        if ((k & 1) == 0) {         // fetch u-pair (+ its tgt for MSE)
            u4  = p4[40 + (k >> 1)];
            tu4 = t4[40 + (k >> 1)];
            float e0 = u4.x - tu4.x, e1 = u4.y - tu4.y;
            float e2 = u4.z - tu4.z, e3 = u4.w - tu4.w;
            mse += e0 * e0 + e1 * e1 + e2 * e2 + e3 * e3;
        }
        float ua = (k & 1) ? u4.z : u4.x;
        float uw = (k & 1) ? u4.w : u4.y;

        // MSE for x_k
        {
            float d0 = x.x - tx.x, d1 = x.y - tx.y;
            float d2 = x.z - tx.z, d3 = x.w - tx.w;
            mse += d0 * d0 + d1 * d1 + d2 * d2 + d3 * d3;
        }

        // dynamics residual (prev in registers, serial in k)
        float s, c;
        __sincosf(prev.z, &s, &c);
        r0 += x.x - (prev.x + prev.w * c * 0.25f);
        r1 += x.y - (prev.y + prev.w * s * 0.25f);
        r2 += x.z - (prev.z + uw * 0.25f);
        r3 += x.w - (prev.w + ua * 0.25f);

        // obstacle terms
        float dx, dy;
        dx = x.x - o0x; dy = x.y - o0y;
        ob += fsqrt_approx(dx * dx + dy * dy) - rad0;
        dx = x.x - o1x; dy = x.y - o1y;
        ob += fsqrt_approx(dx * dx + dy * dy) - rad1;
        dx = x.x - o2x; dy = x.y - o2y;
        ob += fsqrt_approx(dx * dx + dy * dy) - rad2;

        prev = x;
    }

    // per-row dyn norm, fully thread-local (no cross-lane traffic)
    float con = ob + fsqrt_approx(r0 * r0 + r1 * r1 + r2 * r2 + r3 * r3);

    // ---- end-of-kernel reductions (once per thread, not per row) ----
    #pragma unroll
    for (int off = 16; off; off >>= 1) {
        mse += __shfl_xor_sync(FULL, mse, off);
        con += __shfl_xor_sync(FULL, con, off);
    }
    if (lane == 0) {
        s_red[tid >> 5][0] = (double)mse;
        s_red[tid >> 5][1] = (double)con;
    }
    __syncthreads();
    if (tid == 0) {
        double m = s_red[0][0] + s_red[1][0];
        double c = s_red[0][1] + s_red[1][1];
        g_partials[blockIdx.x * 2 + 0] = m;
        g_partials[blockIdx.x * 2 + 1] = c;
        __threadfence();
        unsigned ticket = atomicAdd(&g_count, 1u);
        s_is_last = (ticket == (unsigned)(NBLOCKS - 1));
    }
    __syncthreads();

    // ---- last block: deterministic fixed-order final sum ----
    if (s_is_last) {
        __threadfence();
        __shared__ double sm[NTHREADS];
        __shared__ double sc[NTHREADS];
        double m = 0.0, c = 0.0;
        for (int i = tid; i < NBLOCKS; i += NTHREADS) {
            m += g_partials[2 * i + 0];
            c += g_partials[2 * i + 1];
        }
        sm[tid] = m;
        sc[tid] = c;
        __syncthreads();
        for (int s = NTHREADS / 2; s > 0; s >>= 1) {
            if (tid < s) { sm[tid] += sm[tid + s]; sc[tid] += sc[tid + s]; }
            __syncthreads();
        }
        if (tid == 0) {
            double msev = sm[0] / ((double)B_TOTAL * 240.0);
            double conv = sc[0] / (double)B_TOTAL;
            out[0] = (float)(msev + conv);
            g_count = 0;      // reset for next graph replay
        }
    }
}

extern "C" void kernel_launch(void* const* d_in, const int* in_sizes, int n_in,
                              void* d_out, int out_size)
{
    const float* pred = (const float*)d_in[0];
    const float* tgt  = (const float*)d_in[1];
    const float* inp  = (const float*)d_in[2];
    float* out = (float*)d_out;

    constraint_loss_fused<<<NBLOCKS, NTHREADS>>>(pred, tgt, inp, out);
}